// round 1
// baseline (speedup 1.0000x reference)
#include <cuda_runtime.h>
#include <math.h>

#define BB 512
#define SS 1024
#define TT 52
#define START_TAG 50
#define END_TAG 51

// ---------------- device scratch (no allocations allowed) ----------------
__device__ float  g_E[TT * TT];     // exp(transitions)
__device__ int    g_len[BB];        // per-sequence lengths
__device__ int    g_isU8;           // mask dtype flag
__device__ double g_final[BB];      // per-seq log partition
__device__ double g_gold[BB];       // per-seq gold path score

// ---------------- mask dtype detection ----------------
// Under any 4-byte 0/1 encoding (int32 bool or float32 0.0/1.0), the byte at
// offset b*SS+1 is always 0 (only byte 0 of an int32 "1" is nonzero; float
// 1.0f = 00 00 80 3F has byte1 = 0). Under uint8/bool it equals mask[b][1],
// which is nonzero for any sequence with length >= 2.
__global__ void k_detect(const void* mask) {
    const unsigned char* p = (const unsigned char*)mask;
    int lane = threadIdx.x;
    int any = 0;
    for (int b = lane; b < BB; b += 32)
        any |= (int)p[(size_t)b * SS + 1];
    #pragma unroll
    for (int o = 16; o; o >>= 1) any |= __shfl_xor_sync(0xffffffffu, any, o);
    if (lane == 0) g_isU8 = (any != 0);
}

// ---------------- per-sequence lengths (one warp per row) ----------------
__global__ void k_len(const void* mask) {
    int warp = (blockIdx.x * blockDim.x + threadIdx.x) >> 5;
    int lane = threadIdx.x & 31;
    if (warp >= BB) return;
    int cnt = 0;
    if (g_isU8) {
        const unsigned char* p = (const unsigned char*)mask + (size_t)warp * SS;
        for (int s = lane; s < SS; s += 32) cnt += (p[s] != 0);
    } else {
        const unsigned int* p = (const unsigned int*)mask + (size_t)warp * SS;
        for (int s = lane; s < SS; s += 32) cnt += (p[s] != 0);
    }
    #pragma unroll
    for (int o = 16; o; o >>= 1) cnt += __shfl_xor_sync(0xffffffffu, cnt, o);
    if (lane == 0) g_len[warp] = cnt;
}

// ---------------- E = exp(transitions) ----------------
__global__ void k_exp(const float* __restrict__ tr) {
    int idx = blockIdx.x * blockDim.x + threadIdx.x;
    if (idx < TT * TT) g_E[idx] = expf(tr[idx]);
}

// ---------------- gold path score (one warp per sequence) ----------------
__global__ void k_gold(const float* __restrict__ feats,
                       const int* __restrict__ tags,
                       const float* __restrict__ tr) {
    int warp = (blockIdx.x * blockDim.x + threadIdx.x) >> 5;
    int lane = threadIdx.x & 31;
    if (warp >= BB) return;
    int len = g_len[warp];
    const int* tg = tags + (size_t)warp * SS;
    const float* fb = feats + (size_t)warp * SS * TT;
    double acc = 0.0;
    for (int s = lane; s < len; s += 32) {
        int tag  = tg[s];
        int prev = (s == 0) ? START_TAG : tg[s - 1];
        acc += (double)fb[(size_t)s * TT + tag] + (double)tr[prev * TT + tag];
    }
    #pragma unroll
    for (int o = 16; o; o >>= 1) acc += __shfl_xor_sync(0xffffffffu, acc, o);
    if (lane == 0) {
        int endtag = tg[len - 1];
        g_gold[warp] = acc + (double)tr[endtag * TT + END_TAG];
    }
}

// ---------------- main forward scan: one 64-thread CTA per sequence -------
// Scaled-linear domain: q ∝ exp(part), renormalized each step by an exact
// power of two (exponent extracted from max); base-2 exponent accumulated in
// an integer, converted to log at the end. E column lives in registers.
__global__ void __launch_bounds__(64) k_main(const float* __restrict__ feats,
                                             const float* __restrict__ tr) {
    const int b = blockIdx.x;
    const int j = threadIdx.x;           // 0..63, tags 0..51 active
    const bool act = (j < TT);
    __shared__ __align__(16) float shq[TT];
    __shared__ float shred[2];

    const int len = g_len[b];
    const float* fb = feats + (size_t)b * SS * TT;

    // E column j in registers (coalesced loads: fixed i, contiguous j)
    float Ec[TT];
    #pragma unroll
    for (int i = 0; i < TT; i++) Ec[i] = act ? g_E[i * TT + j] : 0.0f;

    // ---- init: part0 = feats[b,0,:] + trans[START,:] ----
    float p0 = act ? (fb[j] + tr[START_TAG * TT + j]) : -1e30f;
    float m = p0;
    #pragma unroll
    for (int o = 16; o; o >>= 1) m = fmaxf(m, __shfl_xor_sync(0xffffffffu, m, o));
    if ((j & 31) == 0) shred[j >> 5] = m;
    __syncthreads();
    const float m0 = fmaxf(shred[0], shred[1]);
    if (act) shq[j] = exp2f((p0 - m0) * 1.4426950408889634f);
    int Ktot = 0;
    __syncthreads();

    // ---- feats prefetch pipeline (distance 4) ----
    float f0 = 0.f, f1 = 0.f, f2 = 0.f, f3 = 0.f;
    if (act) {
        if (1 < len) f0 = fb[(size_t)1 * TT + j];
        if (2 < len) f1 = fb[(size_t)2 * TT + j];
        if (3 < len) f2 = fb[(size_t)3 * TT + j];
        if (4 < len) f3 = fb[(size_t)4 * TT + j];
    }

    for (int s = 1; s < len; s++) {
        float f = f0; f0 = f1; f1 = f2; f2 = f3;
        int sp = s + 4;
        f3 = (act && sp < len) ? fb[(size_t)sp * TT + j] : 0.0f;

        // matvec: u_j = sum_i q_i * E[i][j]  (q broadcast via LDS.128)
        const float4* q4 = (const float4*)shq;
        float u0 = 0.f, u1 = 0.f, u2 = 0.f, u3 = 0.f;
        #pragma unroll
        for (int c = 0; c < 13; c++) {
            float4 v = q4[c];
            u0 = fmaf(v.x, Ec[4 * c + 0], u0);
            u1 = fmaf(v.y, Ec[4 * c + 1], u1);
            u2 = fmaf(v.z, Ec[4 * c + 2], u2);
            u3 = fmaf(v.w, Ec[4 * c + 3], u3);
        }
        float u = (u0 + u1) + (u2 + u3);
        u *= exp2f(f * 1.4426950408889634f);
        if (!act) u = 0.0f;

        // block max (u >= 0 always, inactive lanes contribute 0)
        float mm = u;
        #pragma unroll
        for (int o = 16; o; o >>= 1) mm = fmaxf(mm, __shfl_xor_sync(0xffffffffu, mm, o));
        if ((j & 31) == 0) shred[j >> 5] = mm;
        __syncthreads();
        mm = fmaxf(shred[0], shred[1]);

        // exact power-of-2 renormalization
        int ex = (__float_as_int(mm) >> 23) & 0xFF;
        Ktot += ex - 127;
        float scale = __int_as_float((254 - ex) << 23);
        if (act) shq[j] = u * scale;
        __syncthreads();
    }

    // ---- final: part_END = C + log( sum_i q_i * E[i][END] ) ----
    float v = act ? shq[j] * g_E[j * TT + END_TAG] : 0.0f;
    #pragma unroll
    for (int o = 16; o; o >>= 1) v += __shfl_xor_sync(0xffffffffu, v, o);
    if ((j & 31) == 0) shred[j >> 5] = v;
    __syncthreads();
    if (j == 0) {
        double dot = (double)shred[0] + (double)shred[1];
        g_final[b] = (double)m0 + (double)Ktot * 0.6931471805599453 + log(dot);
    }
}

// ---------------- final reduction: NLL = sum(final) - sum(gold) ----------
__global__ void k_reduce(float* out) {
    __shared__ double sh[16];
    int tid = threadIdx.x;  // 512 threads
    double a = g_final[tid] - g_gold[tid];
    #pragma unroll
    for (int o = 16; o; o >>= 1) a += __shfl_xor_sync(0xffffffffu, a, o);
    if ((tid & 31) == 0) sh[tid >> 5] = a;
    __syncthreads();
    if (tid < 32) {
        double b = (tid < 16) ? sh[tid] : 0.0;
        #pragma unroll
        for (int o = 8; o; o >>= 1) b += __shfl_xor_sync(0xffffffffu, b, o);
        if (tid == 0) out[0] = (float)b;
    }
}

// ---------------- launch ----------------
extern "C" void kernel_launch(void* const* d_in, const int* in_sizes, int n_in,
                              void* d_out, int out_size) {
    const float* feats = (const float*)d_in[0];
    const void*  mask  = d_in[1];
    const int*   tags  = (const int*)d_in[2];
    const float* tr    = (const float*)d_in[3];
    float* out = (float*)d_out;

    k_detect<<<1, 32>>>(mask);
    k_len<<<16, 1024>>>(mask);                    // 512 warps, one per row
    k_exp<<<(TT * TT + 255) / 256, 256>>>(tr);
    k_gold<<<64, 256>>>(feats, tags, tr);
    k_main<<<BB, 64>>>(feats, tr);
    k_reduce<<<1, 512>>>(out);
}

// round 2
// speedup vs baseline: 1.4548x; 1.4548x over previous
#include <cuda_runtime.h>
#include <math.h>

#define BB 512
#define SS 1024
#define TT 52
#define START_TAG 50
#define END_TAG 51

// ---------------- device scratch (no allocations allowed) ----------------
__device__ float  g_E[TT * TT];     // exp(transitions)
__device__ int    g_len[BB];        // per-sequence lengths
__device__ int    g_isU8;           // mask dtype flag
__device__ double g_final[BB];      // per-seq log partition
__device__ double g_gold[BB];       // per-seq gold path score

// ---------------- mask dtype detection ----------------
// Under any 4-byte 0/1 encoding (int32 bool or float32 0.0/1.0), the byte at
// offset b*SS+1 is always 0. Under uint8/bool it equals mask[b][1], which is
// nonzero for any sequence with length >= 2 (some exist w.h.p.).
__global__ void k_detect(const void* mask) {
    const unsigned char* p = (const unsigned char*)mask;
    int lane = threadIdx.x;
    int any = 0;
    for (int b = lane; b < BB; b += 32)
        any |= (int)p[(size_t)b * SS + 1];
    #pragma unroll
    for (int o = 16; o; o >>= 1) any |= __shfl_xor_sync(0xffffffffu, any, o);
    if (lane == 0) g_isU8 = (any != 0);
}

// ---------------- per-sequence lengths (one warp per row) + zero g_gold ---
__global__ void k_len(const void* mask) {
    int warp = (blockIdx.x * blockDim.x + threadIdx.x) >> 5;
    int lane = threadIdx.x & 31;
    if (warp >= BB) return;
    if (lane == 0) g_gold[warp] = 0.0;   // zero accumulator for k_gold
    int cnt = 0;
    if (g_isU8) {
        const unsigned char* p = (const unsigned char*)mask + (size_t)warp * SS;
        for (int s = lane; s < SS; s += 32) cnt += (p[s] != 0);
    } else {
        const unsigned int* p = (const unsigned int*)mask + (size_t)warp * SS;
        for (int s = lane; s < SS; s += 32) cnt += (p[s] != 0);
    }
    #pragma unroll
    for (int o = 16; o; o >>= 1) cnt += __shfl_xor_sync(0xffffffffu, cnt, o);
    if (lane == 0) g_len[warp] = cnt;
}

// ---------------- E = exp(transitions) ----------------
__global__ void k_exp(const float* __restrict__ tr) {
    int idx = blockIdx.x * blockDim.x + threadIdx.x;
    if (idx < TT * TT) g_E[idx] = expf(tr[idx]);
}

// ---------------- gold path score (4 warps per sequence) ----------------
__global__ void k_gold(const float* __restrict__ feats,
                       const int* __restrict__ tags,
                       const float* __restrict__ tr) {
    int gw   = (blockIdx.x * blockDim.x + threadIdx.x) >> 5;
    int lane = threadIdx.x & 31;
    int row  = gw >> 2;          // sequence
    int q    = gw & 3;           // quarter of the s-range
    if (row >= BB) return;
    int len = g_len[row];
    int s0 = q * (SS / 4);
    int s1 = min(len, s0 + (SS / 4));
    const int* tg = tags + (size_t)row * SS;
    const float* fb = feats + (size_t)row * SS * TT;
    double acc = 0.0;
    for (int s = s0 + lane; s < s1; s += 32) {
        int tag  = tg[s];
        int prev = (s == 0) ? START_TAG : tg[s - 1];
        acc += (double)fb[(size_t)s * TT + tag] + (double)tr[prev * TT + tag];
    }
    #pragma unroll
    for (int o = 16; o; o >>= 1) acc += __shfl_xor_sync(0xffffffffu, acc, o);
    if (lane == 0) {
        if (((len - 1) >> 8) == q)   // this quarter owns the last step
            acc += (double)tr[tg[len - 1] * TT + END_TAG];
        if (acc != 0.0) atomicAdd(&g_gold[row], acc);
        else atomicAdd(&g_gold[row], 0.0);  // keep deterministic write count
    }
}

// ---------------- main forward scan: one 64-thread CTA per sequence -------
// Scaled-linear domain with LAZY power-of-2 renormalization: the shared
// buffer holds the raw step output; every thread derives the (identical)
// scale from the exponent of element 0 — which it already loads as part of
// the matvec — so there is NO max-reduction and only ONE barrier per step
// (double-buffered shq).
__global__ void __launch_bounds__(64) k_main(const float* __restrict__ feats,
                                             const float* __restrict__ tr) {
    const int b = blockIdx.x;
    const int j = threadIdx.x;           // 0..63, tags 0..51 active
    const bool act = (j < TT);
    __shared__ __align__(16) float shq[2][TT];
    __shared__ float shred[2];

    const int len = g_len[b];
    const float* fb = feats + (size_t)b * SS * TT;

    // E column j in registers (coalesced: fixed i, contiguous j)
    float Ec[TT];
    #pragma unroll
    for (int i = 0; i < TT; i++) Ec[i] = act ? g_E[i * TT + j] : 0.0f;

    // ---- init: part0 = feats[b,0,:] + trans[START,:] ----
    float p0 = act ? (fb[j] + tr[START_TAG * TT + j]) : -1e30f;
    float m = p0;
    #pragma unroll
    for (int o = 16; o; o >>= 1) m = fmaxf(m, __shfl_xor_sync(0xffffffffu, m, o));
    if ((j & 31) == 0) shred[j >> 5] = m;
    __syncthreads();
    const float m0 = fmaxf(shred[0], shred[1]);
    if (act) shq[0][j] = exp2f((p0 - m0) * 1.4426950408889634f);
    int Ktot = 0;
    __syncthreads();

    // ---- feats prefetch pipeline (distance 4) ----
    float f0 = 0.f, f1 = 0.f, f2 = 0.f, f3 = 0.f;
    if (act) {
        if (1 < len) f0 = fb[(size_t)1 * TT + j];
        if (2 < len) f1 = fb[(size_t)2 * TT + j];
        if (3 < len) f2 = fb[(size_t)3 * TT + j];
        if (4 < len) f3 = fb[(size_t)4 * TT + j];
    }

    for (int s = 1; s < len; s++) {
        float f = f0; f0 = f1; f1 = f2; f2 = f3;
        int sp = s + 4;
        f3 = (act && sp < len) ? fb[(size_t)sp * TT + j] : 0.0f;

        const float4* q4 = (const float4*)shq[(s - 1) & 1];
        float* wr = shq[s & 1];

        // matvec: u_j = sum_i r_i * E[i][j]  (r broadcast via LDS.128)
        float4 v0 = q4[0];
        float u0 = v0.x * Ec[0];
        float u1 = v0.y * Ec[1];
        float u2 = v0.z * Ec[2];
        float u3 = v0.w * Ec[3];
        #pragma unroll
        for (int c = 1; c < 13; c++) {
            float4 v = q4[c];
            u0 = fmaf(v.x, Ec[4 * c + 0], u0);
            u1 = fmaf(v.y, Ec[4 * c + 1], u1);
            u2 = fmaf(v.z, Ec[4 * c + 2], u2);
            u3 = fmaf(v.w, Ec[4 * c + 3], u3);
        }
        float u = (u0 + u1) + (u2 + u3);

        // representative-exponent renorm: shq[...][0] == v0.x, already loaded
        int ex = ((__float_as_int(v0.x) >> 23) & 0xFF) - 127;
        Ktot += ex;
        float scale = __int_as_float((127 - ex) << 23);   // exact 2^-ex
        u *= scale;
        u *= exp2f(f * 1.4426950408889634f);
        if (act) wr[j] = u;
        __syncthreads();
    }

    // ---- final: part_END = m0 + Ktot*ln2 + log( sum_i r_i * E[i][END] ) --
    const float* rq = shq[(len - 1) & 1];
    float v = act ? rq[j] * g_E[j * TT + END_TAG] : 0.0f;
    #pragma unroll
    for (int o = 16; o; o >>= 1) v += __shfl_xor_sync(0xffffffffu, v, o);
    if ((j & 31) == 0) shred[j >> 5] = v;
    __syncthreads();
    if (j == 0) {
        double dot = (double)shred[0] + (double)shred[1];
        g_final[b] = (double)m0 + (double)Ktot * 0.6931471805599453 + log(dot);
    }
}

// ---------------- final reduction: NLL = sum(final) - sum(gold) ----------
__global__ void k_reduce(float* out) {
    __shared__ double sh[16];
    int tid = threadIdx.x;  // 512 threads
    double a = g_final[tid] - g_gold[tid];
    #pragma unroll
    for (int o = 16; o; o >>= 1) a += __shfl_xor_sync(0xffffffffu, a, o);
    if ((tid & 31) == 0) sh[tid >> 5] = a;
    __syncthreads();
    if (tid < 32) {
        double b = (tid < 16) ? sh[tid] : 0.0;
        #pragma unroll
        for (int o = 8; o; o >>= 1) b += __shfl_xor_sync(0xffffffffu, b, o);
        if (tid == 0) out[0] = (float)b;
    }
}

// ---------------- launch ----------------
extern "C" void kernel_launch(void* const* d_in, const int* in_sizes, int n_in,
                              void* d_out, int out_size) {
    const float* feats = (const float*)d_in[0];
    const void*  mask  = d_in[1];
    const int*   tags  = (const int*)d_in[2];
    const float* tr    = (const float*)d_in[3];
    float* out = (float*)d_out;

    k_detect<<<1, 32>>>(mask);
    k_len<<<16, 1024>>>(mask);                    // 512 warps, one per row
    k_exp<<<(TT * TT + 255) / 256, 256>>>(tr);
    k_gold<<<64, 1024>>>(feats, tags, tr);        // 2048 warps, 4 per row
    k_main<<<BB, 64>>>(feats, tr);
    k_reduce<<<1, 512>>>(out);
}

// round 3
// speedup vs baseline: 1.6240x; 1.1163x over previous
#include <cuda_runtime.h>
#include <math.h>

#define BB 512
#define SS 1024
#define TT 52
#define START_TAG 50
#define END_TAG 51

// ---------------- device scratch (no allocations allowed) ----------------
__device__ float  g_E[TT * TT];      // exp(transitions)
__device__ int    g_len[BB];         // per-sequence lengths
__device__ int    g_isU8;            // mask dtype flag
__device__ double g_final[BB];       // per-seq log partition
__device__ double g_goldp[BB][8];    // per-seq gold partials (8 segments)

// ---------------- packed f32x2 helpers (Blackwell) ----------------
__device__ __forceinline__ unsigned long long f2pack(float lo, float hi) {
    unsigned long long r;
    asm("mov.b64 %0, {%1, %2};" : "=l"(r) : "f"(lo), "f"(hi));
    return r;
}
__device__ __forceinline__ float2 f2unpack(unsigned long long a) {
    float2 r;
    asm("mov.b64 {%0, %1}, %2;" : "=f"(r.x), "=f"(r.y) : "l"(a));
    return r;
}
__device__ __forceinline__ unsigned long long f2fma(unsigned long long a,
                                                    unsigned long long b,
                                                    unsigned long long c) {
    unsigned long long d;
    asm("fma.rn.f32x2 %0, %1, %2, %3;" : "=l"(d) : "l"(a), "l"(b), "l"(c));
    return d;
}
__device__ __forceinline__ unsigned long long f2mul(unsigned long long a,
                                                    unsigned long long b) {
    unsigned long long d;
    asm("mul.rn.f32x2 %0, %1, %2;" : "=l"(d) : "l"(a), "l"(b));
    return d;
}
__device__ __forceinline__ unsigned long long f2add(unsigned long long a,
                                                    unsigned long long b) {
    unsigned long long d;
    asm("add.rn.f32x2 %0, %1, %2;" : "=l"(d) : "l"(a), "l"(b));
    return d;
}
__device__ __forceinline__ float ex2(float x) {
    float y;
    asm("ex2.approx.ftz.f32 %0, %1;" : "=f"(y) : "f"(x));
    return y;
}

// ---------------- mask dtype detection ----------------
// Under any 4-byte 0/1 encoding (int32 bool or float32 0.0/1.0), the byte at
// offset b*SS+1 is always 0. Under uint8/bool it equals mask[b][1], which is
// nonzero for sequences with length >= 2 (exist w.h.p.).
__global__ void k_detect(const void* mask) {
    const unsigned char* p = (const unsigned char*)mask;
    int lane = threadIdx.x;
    int any = 0;
    for (int b = lane; b < BB; b += 32)
        any |= (int)p[(size_t)b * SS + 1];
    #pragma unroll
    for (int o = 16; o; o >>= 1) any |= __shfl_xor_sync(0xffffffffu, any, o);
    if (lane == 0) g_isU8 = (any != 0);
}

// ---------------- per-sequence lengths + E = exp(transitions) fused ------
__global__ void k_len(const void* mask, const float* __restrict__ tr) {
    if (blockIdx.x == 16) {   // E table
        for (int idx = threadIdx.x; idx < TT * TT; idx += blockDim.x)
            g_E[idx] = expf(tr[idx]);
        return;
    }
    int warp = (blockIdx.x * blockDim.x + threadIdx.x) >> 5;
    int lane = threadIdx.x & 31;
    if (warp >= BB) return;
    int cnt = 0;
    if (g_isU8) {
        const unsigned char* p = (const unsigned char*)mask + (size_t)warp * SS;
        for (int s = lane; s < SS; s += 32) cnt += (p[s] != 0);
    } else {
        const unsigned int* p = (const unsigned int*)mask + (size_t)warp * SS;
        for (int s = lane; s < SS; s += 32) cnt += (p[s] != 0);
    }
    #pragma unroll
    for (int o = 16; o; o >>= 1) cnt += __shfl_xor_sync(0xffffffffu, cnt, o);
    if (lane == 0) g_len[warp] = cnt;
}

// ---------------- gold path score (8 warps per sequence, no atomics) -----
__global__ void k_gold(const float* __restrict__ feats,
                       const int* __restrict__ tags,
                       const float* __restrict__ tr) {
    int gw   = (blockIdx.x * blockDim.x + threadIdx.x) >> 5;
    int lane = threadIdx.x & 31;
    int row  = gw >> 3;          // sequence
    int q    = gw & 7;           // eighth of the s-range
    if (row >= BB) return;
    int len = g_len[row];
    int s0 = q << 7;                       // q * 128
    int s1 = min(len, s0 + 128);
    const int* tg = tags + (size_t)row * SS;
    const float* fb = feats + (size_t)row * SS * TT;
    double acc = 0.0;
    for (int s = s0 + lane; s < s1; s += 32) {
        int tag  = tg[s];
        int prev = (s == 0) ? START_TAG : tg[s - 1];
        acc += (double)fb[(size_t)s * TT + tag] + (double)tr[prev * TT + tag];
    }
    #pragma unroll
    for (int o = 16; o; o >>= 1) acc += __shfl_xor_sync(0xffffffffu, acc, o);
    if (lane == 0) {
        if (((len - 1) >> 7) == q)   // this eighth owns the last step
            acc += (double)tr[tg[len - 1] * TT + END_TAG];
        g_goldp[row][q] = acc;
    }
}

// ---------------- main forward scan: one 64-thread CTA per sequence -------
// Scaled-linear domain with lazy exact power-of-2 renorm (representative
// exponent from element 0, already loaded). Matvec uses packed fma.rn.f32x2:
// 26 FFMA2 per thread per step instead of 52 FFMA. One barrier per step
// (double-buffered shq).
__global__ void __launch_bounds__(64) k_main(const float* __restrict__ feats,
                                             const float* __restrict__ tr) {
    const int b = blockIdx.x;
    const int j = threadIdx.x;           // 0..63, tags 0..51 active
    const bool act = (j < TT);
    __shared__ __align__(16) float shq[2][TT];
    __shared__ float shred[2];

    const int len = g_len[b];
    const float* fb = feats + (size_t)b * SS * TT;

    // E column j packed over i-pairs: Ep[c] = (E[2c][j], E[2c+1][j])
    unsigned long long Ep[26];
    #pragma unroll
    for (int c = 0; c < 26; c++) {
        float e0 = act ? g_E[(2 * c) * TT + j] : 0.0f;
        float e1 = act ? g_E[(2 * c + 1) * TT + j] : 0.0f;
        Ep[c] = f2pack(e0, e1);
    }

    // ---- init: part0 = feats[b,0,:] + trans[START,:] ----
    float p0 = act ? (fb[j] + tr[START_TAG * TT + j]) : -1e30f;
    float m = p0;
    #pragma unroll
    for (int o = 16; o; o >>= 1) m = fmaxf(m, __shfl_xor_sync(0xffffffffu, m, o));
    if ((j & 31) == 0) shred[j >> 5] = m;
    __syncthreads();
    const float m0 = fmaxf(shred[0], shred[1]);
    if (act) shq[0][j] = ex2((p0 - m0) * 1.4426950408889634f);
    int Ktot = 0;
    __syncthreads();

    // ---- feats prefetch pipeline (distance 4) ----
    float f0 = 0.f, f1 = 0.f, f2 = 0.f, f3 = 0.f;
    if (act) {
        if (1 < len) f0 = fb[(size_t)1 * TT + j];
        if (2 < len) f1 = fb[(size_t)2 * TT + j];
        if (3 < len) f2 = fb[(size_t)3 * TT + j];
        if (4 < len) f3 = fb[(size_t)4 * TT + j];
    }

    for (int s = 1; s < len; s++) {
        float f = f0; f0 = f1; f1 = f2; f2 = f3;
        int sp = s + 4;
        f3 = (act && sp < len) ? fb[(size_t)sp * TT + j] : 0.0f;

        const ulonglong2* q8 = (const ulonglong2*)shq[(s - 1) & 1];
        float* wr = shq[s & 1];

        // matvec: u_j = sum_i r_i * E[i][j], packed 2 i's per FFMA2
        ulonglong2 v0 = q8[0];
        unsigned long long a0 = f2mul(v0.x, Ep[0]);
        unsigned long long a1 = f2mul(v0.y, Ep[1]);
        unsigned long long a2 = 0ull, a3 = 0ull;
        #pragma unroll
        for (int c = 1; c < 13; c++) {
            ulonglong2 v = q8[c];
            if (c & 1) {
                a2 = f2fma(v.x, Ep[2 * c],     a2);
                a3 = f2fma(v.y, Ep[2 * c + 1], a3);
            } else {
                a0 = f2fma(v.x, Ep[2 * c],     a0);
                a1 = f2fma(v.y, Ep[2 * c + 1], a1);
            }
        }
        a0 = f2add(a0, a2);
        a1 = f2add(a1, a3);
        a0 = f2add(a0, a1);
        float2 h = f2unpack(a0);
        float u = h.x + h.y;

        // representative-exponent renorm: q[0] is lo half of v0.x (loaded)
        float q0 = f2unpack(v0.x).x;
        int ex = ((__float_as_int(q0) >> 23) & 0xFF) - 127;
        Ktot += ex;
        float scale = __int_as_float((127 - ex) << 23);   // exact 2^-ex
        u *= scale;
        u *= ex2(f * 1.4426950408889634f);
        if (act) wr[j] = u;
        __syncthreads();
    }

    // ---- final: part_END = m0 + Ktot*ln2 + log( sum_i r_i * E[i][END] ) --
    const float* rq = shq[(len - 1) & 1];
    float v = act ? rq[j] * g_E[j * TT + END_TAG] : 0.0f;
    #pragma unroll
    for (int o = 16; o; o >>= 1) v += __shfl_xor_sync(0xffffffffu, v, o);
    if ((j & 31) == 0) shred[j >> 5] = v;
    __syncthreads();
    if (j == 0) {
        double dot = (double)shred[0] + (double)shred[1];
        g_final[b] = (double)m0 + (double)Ktot * 0.6931471805599453 + log(dot);
    }
}

// ---------------- final reduction: NLL = sum(final) - sum(gold) ----------
__global__ void k_reduce(float* out) {
    __shared__ double sh[16];
    int tid = threadIdx.x;  // 512 threads
    double g = 0.0;
    #pragma unroll
    for (int q = 0; q < 8; q++) g += g_goldp[tid][q];
    double a = g_final[tid] - g;
    #pragma unroll
    for (int o = 16; o; o >>= 1) a += __shfl_xor_sync(0xffffffffu, a, o);
    if ((tid & 31) == 0) sh[tid >> 5] = a;
    __syncthreads();
    if (tid < 32) {
        double b = (tid < 16) ? sh[tid] : 0.0;
        #pragma unroll
        for (int o = 8; o; o >>= 1) b += __shfl_xor_sync(0xffffffffu, b, o);
        if (tid == 0) out[0] = (float)b;
    }
}

// ---------------- launch ----------------
extern "C" void kernel_launch(void* const* d_in, const int* in_sizes, int n_in,
                              void* d_out, int out_size) {
    const float* feats = (const float*)d_in[0];
    const void*  mask  = d_in[1];
    const int*   tags  = (const int*)d_in[2];
    const float* tr    = (const float*)d_in[3];
    float* out = (float*)d_out;

    k_detect<<<1, 32>>>(mask);
    k_len<<<17, 1024>>>(mask, tr);                // 512 len-warps + 1 exp block
    k_gold<<<128, 1024>>>(feats, tags, tr);       // 4096 warps, 8 per row
    k_main<<<BB, 64>>>(feats, tr);
    k_reduce<<<1, 512>>>(out);
}